// round 2
// baseline (speedup 1.0000x reference)
#include <cuda_runtime.h>
#include <math.h>

#define SEQ    4096
#define HID    1024
#define GRID_C 128
#define ROWS_PER_CTA (HID / GRID_C)   // 8

// Scratch (static __device__ — no allocations allowed)
__device__ float        g_emb[(size_t)SEQ * HID];            // 16 MB
__device__ float        g_U  [(size_t)SEQ * HID];            // 16 MB
__device__ unsigned int g_flag[(size_t)SEQ * GRID_C];        // 2 MB

// ---------------------------------------------------------------------------
// Kernel 1: embedding gather + L2 normalize; also writes h0 -> out row 0 and
// zeroes the per-step flags (required for deterministic graph replays).
// ---------------------------------------------------------------------------
__global__ __launch_bounds__(256) void embed_kernel(const int*   __restrict__ src,
                                                    const float* __restrict__ W,
                                                    const float* __restrict__ h0,
                                                    float*       __restrict__ out)
{
    __shared__ float sred[8];
    __shared__ float sinv;
    const int t   = blockIdx.x;
    const int tid = threadIdx.x;

    if (tid < GRID_C) g_flag[(size_t)t * GRID_C + tid] = 0u;

    const int idx = src[t];
    float4 v = *((const float4*)(W + (size_t)idx * HID) + tid);
    float ss = v.x*v.x + v.y*v.y + v.z*v.z + v.w*v.w;
    #pragma unroll
    for (int off = 16; off > 0; off >>= 1)
        ss += __shfl_xor_sync(0xffffffffu, ss, off);
    if ((tid & 31) == 0) sred[tid >> 5] = ss;
    __syncthreads();
    if (tid == 0) {
        float s = 0.f;
        #pragma unroll
        for (int i = 0; i < 8; i++) s += sred[i];
        sinv = 1.0f / fmaxf(sqrtf(s), 1e-12f);
    }
    __syncthreads();
    const float inv = sinv;
    *((float4*)(g_emb + (size_t)t * HID) + tid) =
        make_float4(v.x*inv, v.y*inv, v.z*inv, v.w*inv);

    if (t == 0) *((float4*)out + tid) = *((const float4*)h0 + tid);
}

// ---------------------------------------------------------------------------
// Kernel 2: U = emb @ W_hi^T + b   (NT GEMM, both operands K-major contiguous)
// 64x64 CTA tile, 256 threads, 4x4 micro-tile, BK=16.
// ---------------------------------------------------------------------------
__global__ __launch_bounds__(256) void gemm_kernel(const float* __restrict__ Whi,
                                                   const float* __restrict__ bias)
{
    __shared__ float As[16][64];
    __shared__ float Bs[16][64];
    const int tid = threadIdx.x;
    const int m0  = blockIdx.y * 64;
    const int n0  = blockIdx.x * 64;
    const int lr  = tid >> 2;          // 0..63 tile row for loads
    const int lk  = (tid & 3) << 2;    // 0,4,8,12
    const int ty  = tid >> 4;          // 0..15
    const int tx  = tid & 15;          // 0..15

    float acc[4][4];
    #pragma unroll
    for (int i = 0; i < 4; i++)
        #pragma unroll
        for (int j = 0; j < 4; j++) acc[i][j] = 0.f;

    for (int k0 = 0; k0 < HID; k0 += 16) {
        float4 a4 = *(const float4*)(g_emb + (size_t)(m0 + lr) * HID + k0 + lk);
        float4 b4 = *(const float4*)(Whi   + (size_t)(n0 + lr) * HID + k0 + lk);
        __syncthreads();
        As[lk+0][lr] = a4.x; As[lk+1][lr] = a4.y; As[lk+2][lr] = a4.z; As[lk+3][lr] = a4.w;
        Bs[lk+0][lr] = b4.x; Bs[lk+1][lr] = b4.y; Bs[lk+2][lr] = b4.z; Bs[lk+3][lr] = b4.w;
        __syncthreads();
        #pragma unroll
        for (int k = 0; k < 16; k++) {
            float4 av = *(const float4*)&As[k][ty * 4];
            float4 bv = *(const float4*)&Bs[k][tx * 4];
            float a[4]  = {av.x, av.y, av.z, av.w};
            float bb[4] = {bv.x, bv.y, bv.z, bv.w};
            #pragma unroll
            for (int i = 0; i < 4; i++)
                #pragma unroll
                for (int j = 0; j < 4; j++)
                    acc[i][j] += a[i] * bb[j];
        }
    }
    #pragma unroll
    for (int i = 0; i < 4; i++) {
        const int row = m0 + ty * 4 + i;
        #pragma unroll
        for (int j = 0; j < 4; j++) {
            const int col = n0 + tx * 4 + j;
            g_U[(size_t)row * HID + col] = acc[i][j] + bias[col];
        }
    }
}

// ---------------------------------------------------------------------------
// Kernel 3: persistent sequential RNN. 128 co-resident CTAs, each owns 8 rows
// of W_hh *in registers* (32 regs/thread). h_t lives in d_out rows; per-step
// readiness is signaled by one flag per producer CTA (no atomic barrier).
// ---------------------------------------------------------------------------
__global__ __launch_bounds__(256) void rnn_kernel(const float* __restrict__ Whh,
                                                  float*       __restrict__ out)
{
    __shared__ float sRed[ROWS_PER_CTA][9];
    const int tid  = threadIdx.x;
    const int lane = tid & 31;
    const int warp = tid >> 5;
    const int rb   = blockIdx.x * ROWS_PER_CTA;

    // Each thread: columns [tid*4, tid*4+4) of rows rb..rb+7, kept in registers.
    float4 w[ROWS_PER_CTA];
    #pragma unroll
    for (int r = 0; r < ROWS_PER_CTA; r++)
        w[r] = *((const float4*)(Whh + (size_t)(rb + r) * HID) + tid);

    volatile unsigned int* flags = g_flag;

    for (int t = 0; t < SEQ; t++) {
        if (t > 0) {
            // wait until every producer CTA published its slice of row t
            if (tid < GRID_C) {
                while (flags[(size_t)(t - 1) * GRID_C + tid] == 0u) { }
            }
            __syncthreads();
            __threadfence();   // acquire: order subsequent h loads after flag loads
        }
        float4 h = __ldcg((const float4*)(out + (size_t)t * HID) + tid);

        float acc[ROWS_PER_CTA];
        #pragma unroll
        for (int r = 0; r < ROWS_PER_CTA; r++)
            acc[r] = w[r].x * h.x + w[r].y * h.y + w[r].z * h.z + w[r].w * h.w;
        #pragma unroll
        for (int r = 0; r < ROWS_PER_CTA; r++) {
            #pragma unroll
            for (int off = 16; off > 0; off >>= 1)
                acc[r] += __shfl_xor_sync(0xffffffffu, acc[r], off);
        }
        if (lane == 0) {
            #pragma unroll
            for (int r = 0; r < ROWS_PER_CTA; r++) sRed[r][warp] = acc[r];
        }
        __syncthreads();
        if (tid < ROWS_PER_CTA) {
            float s = 0.f;
            #pragma unroll
            for (int w8 = 0; w8 < 8; w8++) s += sRed[tid][w8];
            s += g_U[(size_t)t * HID + rb + tid];
            out[(size_t)(t + 1) * HID + rb + tid] = tanhf(s);
            __threadfence();   // make h stores device-visible before flag
        }
        __syncthreads();       // flag store strictly after all 8 fenced stores
        if (tid == 0) flags[(size_t)t * GRID_C + blockIdx.x] = 1u;
    }
}

// ---------------------------------------------------------------------------
extern "C" void kernel_launch(void* const* d_in, const int* in_sizes, int n_in,
                              void* d_out, int out_size)
{
    const int*   src  = (const int*)  d_in[0];
    const float* W    = (const float*)d_in[1];
    const float* h0   = (const float*)d_in[2];
    const float* Whi  = (const float*)d_in[3];
    const float* Whh  = (const float*)d_in[4];
    const float* b    = (const float*)d_in[5];
    float*       out  = (float*)d_out;

    embed_kernel<<<SEQ, 256>>>(src, W, h0, out);
    gemm_kernel<<<dim3(HID / 64, SEQ / 64), 256>>>(Whi, b);
    rnn_kernel<<<GRID_C, 256>>>(Whh, out);
}

// round 3
// speedup vs baseline: 2.8217x; 2.8217x over previous
#include <cuda_runtime.h>
#include <math.h>

#define SEQ    4096
#define HID    1024
#define GRID_C 128
#define ROWS_PER_CTA (HID / GRID_C)   // 8

// Scratch (static __device__ — no allocations allowed)
__device__ float        g_emb[(size_t)SEQ * HID];   // 16 MB
__device__ float        g_U  [(size_t)SEQ * HID];   // 16 MB
__device__ unsigned int g_ctr[SEQ];                 // per-step arrival counter

// ---- scoped memory ops --------------------------------------------------
__device__ __forceinline__ unsigned int ld_acquire_gpu(const unsigned int* p) {
    unsigned int v;
    asm volatile("ld.global.acquire.gpu.u32 %0, [%1];" : "=r"(v) : "l"(p) : "memory");
    return v;
}
__device__ __forceinline__ void red_release_gpu_add(unsigned int* p, unsigned int v) {
    asm volatile("red.release.gpu.global.add.u32 [%0], %1;" :: "l"(p), "r"(v) : "memory");
}

// ---------------------------------------------------------------------------
// Kernel 1: embedding gather + L2 normalize; writes h0 -> out row 0 and zeroes
// the per-step counters (graph-replay determinism).
// ---------------------------------------------------------------------------
__global__ __launch_bounds__(256) void embed_kernel(const int*   __restrict__ src,
                                                    const float* __restrict__ W,
                                                    const float* __restrict__ h0,
                                                    float*       __restrict__ out)
{
    __shared__ float sred[8];
    __shared__ float sinv;
    const int t   = blockIdx.x;
    const int tid = threadIdx.x;

    if (tid == 0) g_ctr[t] = 0u;

    const int idx = src[t];
    float4 v = *((const float4*)(W + (size_t)idx * HID) + tid);
    float ss = v.x*v.x + v.y*v.y + v.z*v.z + v.w*v.w;
    #pragma unroll
    for (int off = 16; off > 0; off >>= 1)
        ss += __shfl_xor_sync(0xffffffffu, ss, off);
    if ((tid & 31) == 0) sred[tid >> 5] = ss;
    __syncthreads();
    if (tid == 0) {
        float s = 0.f;
        #pragma unroll
        for (int i = 0; i < 8; i++) s += sred[i];
        sinv = 1.0f / fmaxf(sqrtf(s), 1e-12f);
    }
    __syncthreads();
    const float inv = sinv;
    *((float4*)(g_emb + (size_t)t * HID) + tid) =
        make_float4(v.x*inv, v.y*inv, v.z*inv, v.w*inv);

    if (t == 0) *((float4*)out + tid) = *((const float4*)h0 + tid);
}

// ---------------------------------------------------------------------------
// Kernel 2: U = emb @ W_hi^T + b   (NT GEMM, both operands K-major contiguous)
// ---------------------------------------------------------------------------
__global__ __launch_bounds__(256) void gemm_kernel(const float* __restrict__ Whi,
                                                   const float* __restrict__ bias)
{
    __shared__ float As[16][64];
    __shared__ float Bs[16][64];
    const int tid = threadIdx.x;
    const int m0  = blockIdx.y * 64;
    const int n0  = blockIdx.x * 64;
    const int lr  = tid >> 2;
    const int lk  = (tid & 3) << 2;
    const int ty  = tid >> 4;
    const int tx  = tid & 15;

    float acc[4][4];
    #pragma unroll
    for (int i = 0; i < 4; i++)
        #pragma unroll
        for (int j = 0; j < 4; j++) acc[i][j] = 0.f;

    for (int k0 = 0; k0 < HID; k0 += 16) {
        float4 a4 = *(const float4*)(g_emb + (size_t)(m0 + lr) * HID + k0 + lk);
        float4 b4 = *(const float4*)(Whi   + (size_t)(n0 + lr) * HID + k0 + lk);
        __syncthreads();
        As[lk+0][lr] = a4.x; As[lk+1][lr] = a4.y; As[lk+2][lr] = a4.z; As[lk+3][lr] = a4.w;
        Bs[lk+0][lr] = b4.x; Bs[lk+1][lr] = b4.y; Bs[lk+2][lr] = b4.z; Bs[lk+3][lr] = b4.w;
        __syncthreads();
        #pragma unroll
        for (int k = 0; k < 16; k++) {
            float4 av = *(const float4*)&As[k][ty * 4];
            float4 bv = *(const float4*)&Bs[k][tx * 4];
            float a[4]  = {av.x, av.y, av.z, av.w};
            float bb[4] = {bv.x, bv.y, bv.z, bv.w};
            #pragma unroll
            for (int i = 0; i < 4; i++)
                #pragma unroll
                for (int j = 0; j < 4; j++)
                    acc[i][j] += a[i] * bb[j];
        }
    }
    #pragma unroll
    for (int i = 0; i < 4; i++) {
        const int row = m0 + ty * 4 + i;
        #pragma unroll
        for (int j = 0; j < 4; j++) {
            const int col = n0 + tx * 4 + j;
            g_U[(size_t)row * HID + col] = acc[i][j] + bias[col];
        }
    }
}

// ---------------------------------------------------------------------------
// Kernel 3: persistent sequential RNN. 128 co-resident CTAs; W_hh slice in
// registers. Per-step grid barrier = 1 release-add per CTA + 1 acquire-poll
// by thread 0 per CTA.
// ---------------------------------------------------------------------------
__global__ __launch_bounds__(256) void rnn_kernel(const float* __restrict__ Whh,
                                                  float*       __restrict__ out)
{
    __shared__ float sRed[ROWS_PER_CTA][9];
    const int tid  = threadIdx.x;
    const int lane = tid & 31;
    const int warp = tid >> 5;
    const int rb   = blockIdx.x * ROWS_PER_CTA;

    // Each thread: columns [tid*4, tid*4+4) of rows rb..rb+7, in registers.
    float4 w[ROWS_PER_CTA];
    #pragma unroll
    for (int r = 0; r < ROWS_PER_CTA; r++)
        w[r] = *((const float4*)(Whh + (size_t)(rb + r) * HID) + tid);

    for (int t = 0; t < SEQ; t++) {
        // Prefetch U (always ready — GEMM kernel completed) before the wait.
        float u = 0.f;
        if (tid < ROWS_PER_CTA) u = __ldcg(g_U + (size_t)t * HID + rb + tid);

        if (t > 0) {
            if (tid == 0) {
                while (ld_acquire_gpu(&g_ctr[t - 1]) < (unsigned)GRID_C) { }
            }
            __syncthreads();   // broadcast readiness + next-iter sRed hazard guard
        }

        float4 h = __ldcg((const float4*)(out + (size_t)t * HID) + tid);

        float acc[ROWS_PER_CTA];
        #pragma unroll
        for (int r = 0; r < ROWS_PER_CTA; r++)
            acc[r] = w[r].x * h.x + w[r].y * h.y + w[r].z * h.z + w[r].w * h.w;
        #pragma unroll
        for (int r = 0; r < ROWS_PER_CTA; r++) {
            #pragma unroll
            for (int off = 16; off > 0; off >>= 1)
                acc[r] += __shfl_xor_sync(0xffffffffu, acc[r], off);
        }
        if (lane == 0) {
            #pragma unroll
            for (int r = 0; r < ROWS_PER_CTA; r++) sRed[r][warp] = acc[r];
        }
        __syncthreads();

        if (tid < ROWS_PER_CTA) {
            float s = u;
            #pragma unroll
            for (int w8 = 0; w8 < 8; w8++) s += sRed[tid][w8];
            out[(size_t)(t + 1) * HID + rb + tid] = tanhf(s);
        }
        // Producer threads (0..7) are all in warp 0: order their stores, then
        // one release-add announces this CTA's slice of row t+1.
        __syncwarp();
        if (tid == 0) red_release_gpu_add(&g_ctr[t], 1u);
        // No trailing __syncthreads: warps racing into t+1 stall at the
        // post-poll __syncthreads before touching sRed again.
    }
}

// ---------------------------------------------------------------------------
extern "C" void kernel_launch(void* const* d_in, const int* in_sizes, int n_in,
                              void* d_out, int out_size)
{
    const int*   src = (const int*)  d_in[0];
    const float* W   = (const float*)d_in[1];
    const float* h0  = (const float*)d_in[2];
    const float* Whi = (const float*)d_in[3];
    const float* Whh = (const float*)d_in[4];
    const float* b   = (const float*)d_in[5];
    float*       out = (float*)d_out;

    embed_kernel<<<SEQ, 256>>>(src, W, h0, out);
    gemm_kernel<<<dim3(HID / 64, SEQ / 64), 256>>>(Whi, b);
    rnn_kernel<<<GRID_C, 256>>>(Whh, out);
}